// round 6
// baseline (speedup 1.0000x reference)
#include <cuda_runtime.h>
#include <cstdint>

#define Hh   128
#define Ww   240
#define NG   40
#define CPG  8
#define ND   48
#define NCC  12
#define WQ   60

#define GWC_CTAS (NG * (Hh / 2))          // 2560 (one CTA = two h rows)
#define CAT_CTAS (Hh * ND)                // 6144
#define TOTAL_CTAS (GWC_CTAS + CAT_CTAS)  // 8704 = 512 * 17

#define ROWB (CPG * Ww * 4)               // 7680B per staged row

__device__ __forceinline__ uint32_t sw128(uint32_t b) {
    return b ^ ((b >> 3) & 0x70);
}

__device__ __forceinline__ unsigned long long pack_f2(float lo, float hi) {
    unsigned long long r;
    asm("mov.b64 %0, {%1, %2};" : "=l"(r) : "f"(lo), "f"(hi));
    return r;
}

// ---------------------------------------------------------------------------
// GWC: out[g][d][h][w] = (1/8) sum_c ref[gc][h][w] * tgt[gc][h][w-d]
// CTA = (g, pair of h rows). 128 threads: t<64 -> row0, t>=64 -> row1.
// Each active thread owns 4 consecutive w. 4-slot sliding register window:
// one 32B refill (2 LDS.128) serves 4 outputs per d. Packed f32x2 FMA.
// ---------------------------------------------------------------------------
__device__ __forceinline__ void gwc_part(
    unsigned char* smem, int g, int hp, int tid,
    const float* __restrict__ refg, const float* __restrict__ tgtg,
    float* __restrict__ out)
{
    const int row = tid >> 6;          // 0 or 1
    const int lt  = tid & 63;
    const int h   = 2 * hp + row;
    unsigned char* srow = smem + row * ROWB;

    // Stage this half's tgt row: transposed [w][c], SW128-swizzled (32B per w).
    {
        const float* tb = tgtg + ((size_t)(g * CPG) * Hh + h) * Ww;
        for (int i = lt; i < CPG * WQ; i += 64) {
            int cc = i / WQ;
            int q  = i - cc * WQ;
            float4 v = *(const float4*)(tb + (size_t)cc * Hh * Ww + 4 * q);
            float vv[4] = {v.x, v.y, v.z, v.w};
#pragma unroll
            for (int j = 0; j < 4; j++)
                *(float*)(srow + sw128((uint32_t)((4 * q + j) * 32 + cc * 4))) = vv[j];
        }
    }

    const bool act = (lt < WQ);
    const int  wb  = 4 * lt;

    // rt64[j][p] = (ref[c=2p](wb+j), ref[c=2p+1](wb+j)) * 1/8, packed f32x2.
    unsigned long long rt64[4][4];
    if (act) {
        const float* rb = refg + ((size_t)(g * CPG) * Hh + h) * Ww + wb;
        float4 rch[8];
#pragma unroll
        for (int cc = 0; cc < 8; cc++)
            rch[cc] = *(const float4*)(rb + (size_t)cc * Hh * Ww);
#pragma unroll
        for (int p = 0; p < 4; p++) {
            const float4 e = rch[2 * p], o = rch[2 * p + 1];
            rt64[0][p] = pack_f2(e.x * 0.125f, o.x * 0.125f);
            rt64[1][p] = pack_f2(e.y * 0.125f, o.y * 0.125f);
            rt64[2][p] = pack_f2(e.z * 0.125f, o.z * 0.125f);
            rt64[3][p] = pack_f2(e.w * 0.125f, o.w * 0.125f);
        }
    }
    __syncthreads();
    if (!act) return;

    // Invariant: win[(j - d) & 3] holds tgt[wb + j - d][0..7] as 4 c-pairs.
    ulonglong2 win[4][2];
#pragma unroll
    for (int k = 0; k < 4; k++) {
        uint32_t b = (uint32_t)((wb + k) * 32);
        win[k][0] = *(const ulonglong2*)(srow + sw128(b));
        win[k][1] = *(const ulonglong2*)(srow + sw128(b + 16));
    }

    float* op = out + (((size_t)g * ND) * Hh + h) * Ww + wb;
#pragma unroll
    for (int d = 0; d < ND; d++) {
        float a[4];
#pragma unroll
        for (int j = 0; j < 4; j++) {
            const int k = (j - d) & 3;
            unsigned long long acc;
            asm("mul.rn.f32x2 %0, %1, %2;"
                : "=l"(acc) : "l"(rt64[j][0]), "l"(win[k][0].x));
            asm("fma.rn.f32x2 %0, %1, %2, %3;"
                : "=l"(acc) : "l"(rt64[j][1]), "l"(win[k][0].y), "l"(acc));
            asm("fma.rn.f32x2 %0, %1, %2, %3;"
                : "=l"(acc) : "l"(rt64[j][2]), "l"(win[k][1].x), "l"(acc));
            asm("fma.rn.f32x2 %0, %1, %2, %3;"
                : "=l"(acc) : "l"(rt64[j][3]), "l"(win[k][1].y), "l"(acc));
            float lo, hi;
            asm("mov.b64 {%0, %1}, %2;" : "=f"(lo), "=f"(hi) : "l"(acc));
            a[j] = lo + hi;
        }
        float4 o; o.x = a[0]; o.y = a[1]; o.z = a[2]; o.w = a[3];
        __stcs((float4*)op, o);
        op += (size_t)Hh * Ww;

        if (d < ND - 1) {
            const int wp   = wb - d - 1;       // new lowest position
            const int slot = (3 - d) & 3;
            if (wp >= 0) {
                uint32_t b = (uint32_t)(wp * 32);
                win[slot][0] = *(const ulonglong2*)(srow + sw128(b));
                win[slot][1] = *(const ulonglong2*)(srow + sw128(b + 16));
            } else {
                win[slot][0] = make_ulonglong2(0ull, 0ull);
                win[slot][1] = make_ulonglong2(0ull, 0ull);
            }
        }
    }
}

// ---------------------------------------------------------------------------
// Concat: CTA per (h, d). Channels 40..51 = ref masked (w>=d),
// 52..63 = tgt shifted right by d. Funnel-shift of two aligned float4 loads;
// shift s = d&3 is CTA-uniform -> template instantiation, static selects.
// ---------------------------------------------------------------------------
template <int S>
__device__ __forceinline__ void cat_inner(
    int h, int d, int t,
    const float* __restrict__ rc, const float* __restrict__ tc,
    float* __restrict__ out)
{
    if (t >= 120) return;
    const int half = (t >= 60) ? 1 : 0;
    const int q    = t - 60 * half;
    const int a    = d >> 2;
    const int wb   = 4 * q;
    const size_t hw = (size_t)Hh * Ww;

#pragma unroll
    for (int i = 0; i < 12; i++) {
        const int cc = half + 2 * i;      // 0..23
        float4 o;
        if (i < 6) {
            // ref channel cc, masked where w < d
            float4 v = *(const float4*)(rc + ((size_t)cc * Hh + h) * Ww + wb);
            o.x = (wb + 0 >= d) ? v.x : 0.f;
            o.y = (wb + 1 >= d) ? v.y : 0.f;
            o.z = (wb + 2 >= d) ? v.z : 0.f;
            o.w = (wb + 3 >= d) ? v.w : 0.f;
        } else {
            // tgt channel cc-12, shifted right by d
            const int ch = cc - NCC;
            const float* row = tc + ((size_t)ch * Hh + h) * Ww;
            const int c1 = q - a, c0 = q - a - 1;
            float4 v1 = (c1 >= 0) ? *(const float4*)(row + 4 * c1)
                                  : make_float4(0.f, 0.f, 0.f, 0.f);
            float4 v0 = (c0 >= 0) ? *(const float4*)(row + 4 * c0)
                                  : make_float4(0.f, 0.f, 0.f, 0.f);
            if (S == 0)      { o = v1; }
            else if (S == 1) { o.x = v0.w; o.y = v1.x; o.z = v1.y; o.w = v1.z; }
            else if (S == 2) { o.x = v0.z; o.y = v0.w; o.z = v1.x; o.w = v1.y; }
            else             { o.x = v0.y; o.y = v0.z; o.z = v0.w; o.w = v1.x; }
        }
        __stcs((float4*)(out + ((size_t)(NG + cc) * ND + d) * hw + h * Ww + wb), o);
    }
}

// ---------------------------------------------------------------------------
__global__ void __launch_bounds__(128, 6) fused_kernel(
    const float* __restrict__ refg, const float* __restrict__ tgtg,
    const float* __restrict__ rc,   const float* __restrict__ tc,
    float* __restrict__ out)
{
    __shared__ __align__(16) unsigned char smem[2 * ROWB];  // 15360B

    const int bx  = blockIdx.x;
    const int tid = threadIdx.x;
    const int qq  = bx / 17;
    const int r   = bx - qq * 17;

    if (r < 5) {
        const int idx = qq * 5 + r;          // 0..2559
        gwc_part(smem, idx / (Hh / 2), idx % (Hh / 2), tid, refg, tgtg, out);
    } else {
        const int idx = qq * 12 + (r - 5);   // 0..6143
        const int d = idx / Hh;
        const int h = idx % Hh;
        switch (d & 3) {
            case 0: cat_inner<0>(h, d, tid, rc, tc, out); break;
            case 1: cat_inner<1>(h, d, tid, rc, tc, out); break;
            case 2: cat_inner<2>(h, d, tid, rc, tc, out); break;
            default: cat_inner<3>(h, d, tid, rc, tc, out); break;
        }
    }
}

extern "C" void kernel_launch(void* const* d_in, const int* in_sizes, int n_in,
                              void* d_out, int out_size)
{
    const float* refg = (const float*)d_in[0];  // ref_gwc    [320,128,240]
    const float* tgtg = (const float*)d_in[1];  // tgt_gwc    [320,128,240]
    const float* rc   = (const float*)d_in[2];  // ref_concat [12,128,240]
    const float* tc   = (const float*)d_in[3];  // tgt_concat [12,128,240]
    float* out = (float*)d_out;                 // [64,48,128,240]

    fused_kernel<<<TOTAL_CTAS, 128>>>(refg, tgtg, rc, tc, out);
}